// round 1
// baseline (speedup 1.0000x reference)
#include <cuda_runtime.h>
#include <math.h>

#define BATCH 4
#define SEQ   4096
#define FEAT  1024
#define HID   1024

// Scratch (device globals — allocation-free per harness rules)
__device__ float g_q[BATCH * SEQ * HID];            // 64 MB
__device__ float g_k[BATCH * SEQ * HID];            // 64 MB
__device__ float g_v[BATCH * SEQ * HID];            // 64 MB
__device__ float g_p[BATCH * SEQ * SEQ];            // 256 MB (scores / probs)

// ---------------------------------------------------------------------------
// Classic 128x128x8 tiled SGEMM, NN layout (row-major A[MxK], B[KxN]),
// optional bias add. 256 threads, 8x8 per thread. All dims divide tiles.
// ---------------------------------------------------------------------------
template <bool ADD_BIAS>
__global__ __launch_bounds__(256)
void sgemm_nn(const float* __restrict__ A, const float* __restrict__ B,
              const float* __restrict__ bias, float* __restrict__ C,
              int M, int N, int K,
              long long sA, long long sB, long long sC)
{
    constexpr int BM = 128, BN = 128, BK = 8, TM = 8, TN = 8;
    __shared__ float As[BK][BM];
    __shared__ float Bs[BK][BN];

    const int bz = blockIdx.z;
    A += sA * bz; B += sB * bz; C += sC * bz;

    const int tm0 = blockIdx.y * BM;
    const int tn0 = blockIdx.x * BN;
    const int tid = threadIdx.x;
    const int tr  = (tid >> 4) * TM;     // thread row offset in tile
    const int tc  = (tid & 15) * TN;     // thread col offset in tile

    // A tile load: 128 rows x 8 cols -> one float4 per thread (transposed store)
    const int arow = tid >> 1, acol = (tid & 1) * 4;
    // B tile load: 8 rows x 128 cols -> one float4 per thread (direct store)
    const int brow = tid >> 5, bcol = (tid & 31) * 4;

    const float* Aptr = A + (long long)(tm0 + arow) * K + acol;
    const float* Bptr = B + (long long)brow * N + tn0 + bcol;

    float acc[TM][TN];
    #pragma unroll
    for (int i = 0; i < TM; i++)
        #pragma unroll
        for (int j = 0; j < TN; j++) acc[i][j] = 0.f;

    for (int k0 = 0; k0 < K; k0 += BK) {
        float4 av = *(const float4*)(Aptr + k0);
        As[acol + 0][arow] = av.x;
        As[acol + 1][arow] = av.y;
        As[acol + 2][arow] = av.z;
        As[acol + 3][arow] = av.w;
        float4 bv = *(const float4*)(Bptr + (long long)k0 * N);
        *(float4*)&Bs[brow][bcol] = bv;
        __syncthreads();

        #pragma unroll
        for (int kk = 0; kk < BK; kk++) {
            float ra[TM], rb[TN];
            #pragma unroll
            for (int i = 0; i < TM; i++) ra[i] = As[kk][tr + i];
            #pragma unroll
            for (int j = 0; j < TN; j++) rb[j] = Bs[kk][tc + j];
            #pragma unroll
            for (int i = 0; i < TM; i++)
                #pragma unroll
                for (int j = 0; j < TN; j++)
                    acc[i][j] = fmaf(ra[i], rb[j], acc[i][j]);
        }
        __syncthreads();
    }

    #pragma unroll
    for (int i = 0; i < TM; i++) {
        long long crow = (long long)(tm0 + tr + i) * N + tn0 + tc;
        #pragma unroll
        for (int j = 0; j < TN; j += 4) {
            float4 v = make_float4(acc[i][j], acc[i][j+1], acc[i][j+2], acc[i][j+3]);
            if (ADD_BIAS) {
                v.x += bias[tn0 + tc + j + 0];
                v.y += bias[tn0 + tc + j + 1];
                v.z += bias[tn0 + tc + j + 2];
                v.w += bias[tn0 + tc + j + 3];
            }
            *(float4*)&C[crow + j] = v;
        }
    }
}

// ---------------------------------------------------------------------------
// NT SGEMM with output scale: C[m][n] = alpha * sum_k A[m][k] * B[n][k].
// Both A and B row-major with leading dim K. Same tiling as above.
// ---------------------------------------------------------------------------
__global__ __launch_bounds__(256)
void sgemm_nt_scaled(const float* __restrict__ A, const float* __restrict__ B,
                     float* __restrict__ C, int M, int N, int K, float alpha,
                     long long sA, long long sB, long long sC)
{
    constexpr int BM = 128, BN = 128, BK = 8, TM = 8, TN = 8;
    __shared__ float As[BK][BM];
    __shared__ float Bs[BK][BN];

    const int bz = blockIdx.z;
    A += sA * bz; B += sB * bz; C += sC * bz;

    const int tm0 = blockIdx.y * BM;
    const int tn0 = blockIdx.x * BN;
    const int tid = threadIdx.x;
    const int tr  = (tid >> 4) * TM;
    const int tc  = (tid & 15) * TN;

    const int lrow = tid >> 1, lcol = (tid & 1) * 4;   // 128 rows x 8 k-cols

    const float* Aptr = A + (long long)(tm0 + lrow) * K + lcol;
    const float* Bptr = B + (long long)(tn0 + lrow) * K + lcol;

    float acc[TM][TN];
    #pragma unroll
    for (int i = 0; i < TM; i++)
        #pragma unroll
        for (int j = 0; j < TN; j++) acc[i][j] = 0.f;

    for (int k0 = 0; k0 < K; k0 += BK) {
        float4 av = *(const float4*)(Aptr + k0);
        As[lcol + 0][lrow] = av.x;
        As[lcol + 1][lrow] = av.y;
        As[lcol + 2][lrow] = av.z;
        As[lcol + 3][lrow] = av.w;
        float4 bv = *(const float4*)(Bptr + k0);
        Bs[lcol + 0][lrow] = bv.x;
        Bs[lcol + 1][lrow] = bv.y;
        Bs[lcol + 2][lrow] = bv.z;
        Bs[lcol + 3][lrow] = bv.w;
        __syncthreads();

        #pragma unroll
        for (int kk = 0; kk < BK; kk++) {
            float ra[TM], rb[TN];
            #pragma unroll
            for (int i = 0; i < TM; i++) ra[i] = As[kk][tr + i];
            #pragma unroll
            for (int j = 0; j < TN; j++) rb[j] = Bs[kk][tc + j];
            #pragma unroll
            for (int i = 0; i < TM; i++)
                #pragma unroll
                for (int j = 0; j < TN; j++)
                    acc[i][j] = fmaf(ra[i], rb[j], acc[i][j]);
        }
        __syncthreads();
    }

    #pragma unroll
    for (int i = 0; i < TM; i++) {
        long long crow = (long long)(tm0 + tr + i) * N + tn0 + tc;
        #pragma unroll
        for (int j = 0; j < TN; j += 4) {
            float4 v = make_float4(alpha * acc[i][j],   alpha * acc[i][j+1],
                                   alpha * acc[i][j+2], alpha * acc[i][j+3]);
            *(float4*)&C[crow + j] = v;
        }
    }
}

// ---------------------------------------------------------------------------
// Row softmax over SEQ=4096 columns. One block (256 threads) per row;
// the row lives entirely in registers (16 floats/thread): 1 read + 1 write.
// ---------------------------------------------------------------------------
__global__ __launch_bounds__(256)
void softmax_rows(float* __restrict__ P)
{
    float* p = P + (long long)blockIdx.x * SEQ;
    const int tid = threadIdx.x;
    __shared__ float redm[8];
    __shared__ float reds[8];

    float4 r[4];
    float m = -3.0e38f;
    #pragma unroll
    for (int j = 0; j < 4; j++) {
        r[j] = *(const float4*)(p + tid * 4 + j * 1024);
        m = fmaxf(m, fmaxf(fmaxf(r[j].x, r[j].y), fmaxf(r[j].z, r[j].w)));
    }
    #pragma unroll
    for (int off = 16; off; off >>= 1)
        m = fmaxf(m, __shfl_xor_sync(0xffffffffu, m, off));
    if ((tid & 31) == 0) redm[tid >> 5] = m;
    __syncthreads();
    m = redm[0];
    #pragma unroll
    for (int i = 1; i < 8; i++) m = fmaxf(m, redm[i]);

    float s = 0.f;
    #pragma unroll
    for (int j = 0; j < 4; j++) {
        r[j].x = __expf(r[j].x - m);
        r[j].y = __expf(r[j].y - m);
        r[j].z = __expf(r[j].z - m);
        r[j].w = __expf(r[j].w - m);
        s += (r[j].x + r[j].y) + (r[j].z + r[j].w);
    }
    #pragma unroll
    for (int off = 16; off; off >>= 1)
        s += __shfl_xor_sync(0xffffffffu, s, off);
    if ((tid & 31) == 0) reds[tid >> 5] = s;
    __syncthreads();
    s = 0.f;
    #pragma unroll
    for (int i = 0; i < 8; i++) s += reds[i];

    const float inv = 1.0f / s;
    #pragma unroll
    for (int j = 0; j < 4; j++) {
        r[j].x *= inv; r[j].y *= inv; r[j].z *= inv; r[j].w *= inv;
        *(float4*)(p + tid * 4 + j * 1024) = r[j];
    }
}

// ---------------------------------------------------------------------------
extern "C" void kernel_launch(void* const* d_in, const int* in_sizes, int n_in,
                              void* d_out, int out_size)
{
    const float* x  = (const float*)d_in[0];
    const float* Wq = (const float*)d_in[1];
    const float* bq = (const float*)d_in[2];
    const float* Wk = (const float*)d_in[3];
    const float* bk = (const float*)d_in[4];
    const float* Wv = (const float*)d_in[5];
    const float* bv = (const float*)d_in[6];
    float* out = (float*)d_out;

    float *q, *k, *v, *p;
    cudaGetSymbolAddress((void**)&q, g_q);
    cudaGetSymbolAddress((void**)&k, g_k);
    cudaGetSymbolAddress((void**)&v, g_v);
    cudaGetSymbolAddress((void**)&p, g_p);

    // 1) QKV projections: [16384,1024] x [1024,1024] + bias
    dim3 gqkv(HID / 128, (BATCH * SEQ) / 128, 1);
    sgemm_nn<true><<<gqkv, 256>>>(x, Wq, bq, q, BATCH * SEQ, HID, FEAT, 0, 0, 0);
    sgemm_nn<true><<<gqkv, 256>>>(x, Wk, bk, k, BATCH * SEQ, HID, FEAT, 0, 0, 0);
    sgemm_nn<true><<<gqkv, 256>>>(x, Wv, bv, v, BATCH * SEQ, HID, FEAT, 0, 0, 0);

    // 2) scores = (Q K^T) / 32, batched over B
    dim3 gs(SEQ / 128, SEQ / 128, BATCH);
    sgemm_nt_scaled<<<gs, 256>>>(q, k, p, SEQ, SEQ, HID, 1.0f / 32.0f,
                                 (long long)SEQ * HID, (long long)SEQ * HID,
                                 (long long)SEQ * SEQ);

    // 3) row softmax over 4096 columns, B*S rows
    softmax_rows<<<BATCH * SEQ, 256>>>(p);

    // 4) out = P V, batched over B
    dim3 go(HID / 128, SEQ / 128, BATCH);
    sgemm_nn<false><<<go, 256>>>(p, v, nullptr, out, SEQ, HID, SEQ,
                                 (long long)SEQ * SEQ, (long long)SEQ * HID,
                                 (long long)SEQ * HID);
}

// round 3
// speedup vs baseline: 3.7617x; 3.7617x over previous
#include <cuda_runtime.h>
#include <cstdint>
#include <math.h>

#define BATCH 4
#define SEQ   4096
#define FEAT  1024
#define HID   1024

// ---------------------------------------------------------------------------
// Scratch (device globals — allocation-free per harness rules)
// ---------------------------------------------------------------------------
__device__ float g_xc [BATCH * SEQ * FEAT];   // tf32-rounded x        64 MB
__device__ float g_wqt[FEAT * HID];           // Wq^T (tf32)            4 MB
__device__ float g_wkt[FEAT * HID];           // Wk^T (tf32)            4 MB
__device__ float g_wvt[FEAT * HID];           // Wv^T (tf32)            4 MB
__device__ float g_q  [BATCH * SEQ * HID];    // Q (tf32-rounded)      64 MB
__device__ float g_k  [BATCH * SEQ * HID];    // K (tf32-rounded)      64 MB
__device__ float g_v  [BATCH * SEQ * HID];    // V (tf32-rounded)      64 MB
__device__ float g_vt [BATCH * HID * SEQ];    // V^T per batch         64 MB
__device__ float g_p  [(size_t)BATCH * SEQ * SEQ]; // scores/probs    256 MB

// ---------------------------------------------------------------------------
// helpers
// ---------------------------------------------------------------------------
__device__ __forceinline__ uint32_t smem_u32(const void* p) {
    uint32_t a;
    asm("{ .reg .u64 t; cvta.to.shared.u64 t, %1; cvt.u32.u64 %0, t; }"
        : "=r"(a) : "l"(p));
    return a;
}

__device__ __forceinline__ float to_tf32(float x) {
    uint32_t u;
    asm("cvt.rn.tf32.f32 %0, %1;" : "=r"(u) : "f"(x));
    return __uint_as_float(u);
}

__device__ __forceinline__ void cp_async16(uint32_t s, const float* g) {
    asm volatile("cp.async.cg.shared.global [%0], [%1], 16;"
                 :: "r"(s), "l"(__cvta_generic_to_global((const void*)g)) : "memory");
}

__device__ __forceinline__ void mma_tf32(float* c, const uint32_t* a, const uint32_t* b) {
    asm volatile(
        "mma.sync.aligned.m16n8k8.row.col.f32.tf32.tf32.f32 "
        "{%0,%1,%2,%3}, {%4,%5,%6,%7}, {%8,%9}, {%0,%1,%2,%3};"
        : "+f"(c[0]), "+f"(c[1]), "+f"(c[2]), "+f"(c[3])
        : "r"(a[0]), "r"(a[1]), "r"(a[2]), "r"(a[3]), "r"(b[0]), "r"(b[1]));
}

// ---------------------------------------------------------------------------
// tf32 mma.sync GEMM (NT): C[m][n] = alpha * sum_k A[m][k]*B[n][k] (+bias)
// BM=128, BN=256, BK=32, 3 stages, 256 threads (8 warps, 2x4 -> 64x64/warp)
// ---------------------------------------------------------------------------
#define GBM 128
#define GBN 256
#define GBK 32
#define GST 3
#define AST 40                                  // padded row stride (floats)
#define A_FLTS (GBM * AST)                      // 5120
#define B_FLTS (GBN * AST)                      // 10240
#define STAGE_FLTS (A_FLTS + B_FLTS)            // 15360
#define GEMM_SMEM (GST * STAGE_FLTS * 4)        // 184320 bytes

template <bool ADD_BIAS, bool ROUND_OUT>
__global__ __launch_bounds__(256, 1)
void gemm_mma(const float* __restrict__ A, const float* __restrict__ B,
              const float* __restrict__ bias, float* __restrict__ C,
              int K, int ldc, float alpha,
              long long sA, long long sB, long long sC)
{
    extern __shared__ float sm[];
    const uint32_t sbase = smem_u32(sm);

    const int tid = threadIdx.x;
    const int wid = tid >> 5, lane = tid & 31;
    const int g = lane >> 2, t = lane & 3;          // quad row / quad lane
    const int wm = wid >> 2, wn = wid & 3;          // 2 x 4 warp grid
    const int wm0 = wm * 64, wn0 = wn * 64;
    const int fl = (g >> 2) & 1;                    // per-thread chunk flip

    const int bz = blockIdx.z;
    A += sA * bz; B += sB * bz; C += sC * bz;
    const int m0 = blockIdx.y * GBM;
    const int n0 = blockIdx.x * GBN;

    const int NITER = K / GBK;

    auto load_stage = [&](int c) {
        const int slot = c % GST;
        const uint32_t s_a = sbase + slot * STAGE_FLTS * 4;
        const uint32_t s_b = s_a + A_FLTS * 4;
        const long long koff = (long long)c * GBK;
        #pragma unroll
        for (int i = 0; i < 4; i++) {               // A: 1024 16B chunks
            int s = tid + i * 256;
            int row = s >> 3, ch = s & 7;
            int chs = ch ^ ((row >> 2) & 1);
            cp_async16(s_a + (uint32_t)(row * AST + chs * 4) * 4,
                       A + (long long)(m0 + row) * K + koff + ch * 4);
        }
        #pragma unroll
        for (int i = 0; i < 8; i++) {               // B: 2048 16B chunks
            int s = tid + i * 256;
            int row = s >> 3, ch = s & 7;
            int chs = ch ^ ((row >> 2) & 1);
            cp_async16(s_b + (uint32_t)(row * AST + chs * 4) * 4,
                       B + (long long)(n0 + row) * K + koff + ch * 4);
        }
        asm volatile("cp.async.commit_group;" ::: "memory");
    };

    float acc[4][8][4];
    #pragma unroll
    for (int mi = 0; mi < 4; mi++)
        #pragma unroll
        for (int ni = 0; ni < 8; ni++)
            #pragma unroll
            for (int r = 0; r < 4; r++) acc[mi][ni][r] = 0.f;

    load_stage(0);
    if (NITER > 1) load_stage(1);

    for (int it = 0; it < NITER; it++) {
        if (it < NITER - 1)
            asm volatile("cp.async.wait_group 1;" ::: "memory");
        else
            asm volatile("cp.async.wait_group 0;" ::: "memory");
        __syncthreads();

        if (it + 2 < NITER) load_stage(it + 2);

        const int slot = it % GST;
        const float* as = sm + slot * STAGE_FLTS + wm0 * AST;
        const float* bs = sm + slot * STAGE_FLTS + A_FLTS + wn0 * AST;
        const uint32_t* asu = (const uint32_t*)as;
        const uint32_t* bsu = (const uint32_t*)bs;

        #pragma unroll
        for (int kk = 0; kk < 4; kk++) {
            const int c0 = (2 * kk) ^ fl;           // chunk slot holding k0..k0+3
            const int c1 = (2 * kk + 1) ^ fl;       // chunk slot holding k0+4..k0+7
            uint32_t a[4][4];
            #pragma unroll
            for (int mi = 0; mi < 4; mi++) {
                int r0 = (mi * 16 + g) * AST;
                int r1 = r0 + 8 * AST;
                a[mi][0] = asu[r0 + c0 * 4 + t];
                a[mi][1] = asu[r1 + c0 * 4 + t];
                a[mi][2] = asu[r0 + c1 * 4 + t];
                a[mi][3] = asu[r1 + c1 * 4 + t];
            }
            uint32_t b[8][2];
            #pragma unroll
            for (int ni = 0; ni < 8; ni++) {
                int rb = (ni * 8 + g) * AST;
                b[ni][0] = bsu[rb + c0 * 4 + t];
                b[ni][1] = bsu[rb + c1 * 4 + t];
            }
            #pragma unroll
            for (int mi = 0; mi < 4; mi++)
                #pragma unroll
                for (int ni = 0; ni < 8; ni++)
                    mma_tf32(acc[mi][ni], a[mi], b[ni]);
        }
        __syncthreads();
    }

    // epilogue: registers -> gmem with fused alpha/bias/round
    #pragma unroll
    for (int ni = 0; ni < 8; ni++) {
        const int col = n0 + wn0 + ni * 8 + t * 2;
        float2 bv = make_float2(0.f, 0.f);
        if (ADD_BIAS) bv = *(const float2*)(bias + col);
        #pragma unroll
        for (int mi = 0; mi < 4; mi++) {
            const int row0 = m0 + wm0 + mi * 16 + g;
            float v0 = fmaf(alpha, acc[mi][ni][0], bv.x);
            float v1 = fmaf(alpha, acc[mi][ni][1], bv.y);
            float v2 = fmaf(alpha, acc[mi][ni][2], bv.x);
            float v3 = fmaf(alpha, acc[mi][ni][3], bv.y);
            if (ROUND_OUT) {
                v0 = to_tf32(v0); v1 = to_tf32(v1);
                v2 = to_tf32(v2); v3 = to_tf32(v3);
            }
            *(float2*)(C + (long long)row0 * ldc + col)       = make_float2(v0, v1);
            *(float2*)(C + (long long)(row0 + 8) * ldc + col) = make_float2(v2, v3);
        }
    }
}

// ---------------------------------------------------------------------------
// x -> tf32-rounded copy
// ---------------------------------------------------------------------------
__global__ __launch_bounds__(256)
void convert_tf32_kernel(const float4* __restrict__ in, float4* __restrict__ out, int n4)
{
    int i = blockIdx.x * 256 + threadIdx.x;
    if (i < n4) {
        float4 v = in[i];
        v.x = to_tf32(v.x); v.y = to_tf32(v.y); v.z = to_tf32(v.z); v.w = to_tf32(v.w);
        out[i] = v;
    }
}

// ---------------------------------------------------------------------------
// Transpose with tf32 rounding: out[c][r] = tf32(in[r][c]); in [R x Cc]
// ---------------------------------------------------------------------------
__global__ __launch_bounds__(256)
void transpose_tf32(const float* __restrict__ in, float* __restrict__ out,
                    int R, int Cc, long long sIn, long long sOut)
{
    __shared__ float tbuf[32][33];
    const int bz = blockIdx.z;
    in += sIn * bz; out += sOut * bz;
    const int c0 = blockIdx.x * 32, r0 = blockIdx.y * 32;
    const int x = threadIdx.x, y = threadIdx.y;   // (32, 8)
    #pragma unroll
    for (int i = 0; i < 32; i += 8)
        tbuf[y + i][x] = in[(long long)(r0 + y + i) * Cc + c0 + x];
    __syncthreads();
    #pragma unroll
    for (int i = 0; i < 32; i += 8)
        out[(long long)(c0 + y + i) * R + r0 + x] = to_tf32(tbuf[x][y + i]);
}

// ---------------------------------------------------------------------------
// Row softmax over SEQ=4096 cols, output rounded to tf32 (next MMA operand)
// ---------------------------------------------------------------------------
__global__ __launch_bounds__(256)
void softmax_rows(float* __restrict__ P)
{
    float* p = P + (long long)blockIdx.x * SEQ;
    const int tid = threadIdx.x;
    __shared__ float redm[8];
    __shared__ float reds[8];

    float4 r[4];
    float m = -3.0e38f;
    #pragma unroll
    for (int j = 0; j < 4; j++) {
        r[j] = *(const float4*)(p + tid * 4 + j * 1024);
        m = fmaxf(m, fmaxf(fmaxf(r[j].x, r[j].y), fmaxf(r[j].z, r[j].w)));
    }
    #pragma unroll
    for (int off = 16; off; off >>= 1)
        m = fmaxf(m, __shfl_xor_sync(0xffffffffu, m, off));
    if ((tid & 31) == 0) redm[tid >> 5] = m;
    __syncthreads();
    m = redm[0];
    #pragma unroll
    for (int i = 1; i < 8; i++) m = fmaxf(m, redm[i]);

    float s = 0.f;
    #pragma unroll
    for (int j = 0; j < 4; j++) {
        r[j].x = __expf(r[j].x - m);
        r[j].y = __expf(r[j].y - m);
        r[j].z = __expf(r[j].z - m);
        r[j].w = __expf(r[j].w - m);
        s += (r[j].x + r[j].y) + (r[j].z + r[j].w);
    }
    #pragma unroll
    for (int off = 16; off; off >>= 1)
        s += __shfl_xor_sync(0xffffffffu, s, off);
    if ((tid & 31) == 0) reds[tid >> 5] = s;
    __syncthreads();
    s = 0.f;
    #pragma unroll
    for (int i = 0; i < 8; i++) s += reds[i];

    const float inv = 1.0f / s;
    #pragma unroll
    for (int j = 0; j < 4; j++) {
        r[j].x = to_tf32(r[j].x * inv);
        r[j].y = to_tf32(r[j].y * inv);
        r[j].z = to_tf32(r[j].z * inv);
        r[j].w = to_tf32(r[j].w * inv);
        *(float4*)(p + tid * 4 + j * 1024) = r[j];
    }
}

// ---------------------------------------------------------------------------
extern "C" void kernel_launch(void* const* d_in, const int* in_sizes, int n_in,
                              void* d_out, int out_size)
{
    const float* x  = (const float*)d_in[0];
    const float* Wq = (const float*)d_in[1];
    const float* bq = (const float*)d_in[2];
    const float* Wk = (const float*)d_in[3];
    const float* bk = (const float*)d_in[4];
    const float* Wv = (const float*)d_in[5];
    const float* bv = (const float*)d_in[6];
    float* out = (float*)d_out;

    float *xc, *wqt, *wkt, *wvt, *q, *k, *v, *vt, *p;
    cudaGetSymbolAddress((void**)&xc,  g_xc);
    cudaGetSymbolAddress((void**)&wqt, g_wqt);
    cudaGetSymbolAddress((void**)&wkt, g_wkt);
    cudaGetSymbolAddress((void**)&wvt, g_wvt);
    cudaGetSymbolAddress((void**)&q,   g_q);
    cudaGetSymbolAddress((void**)&k,   g_k);
    cudaGetSymbolAddress((void**)&v,   g_v);
    cudaGetSymbolAddress((void**)&vt,  g_vt);
    cudaGetSymbolAddress((void**)&p,   g_p);

    cudaFuncSetAttribute(gemm_mma<true,  true >, cudaFuncAttributeMaxDynamicSharedMemorySize, GEMM_SMEM);
    cudaFuncSetAttribute(gemm_mma<false, false>, cudaFuncAttributeMaxDynamicSharedMemorySize, GEMM_SMEM);

    // 0) tf32-round x
    convert_tf32_kernel<<<(BATCH * SEQ * FEAT / 4 + 255) / 256, 256>>>(
        (const float4*)x, (float4*)xc, BATCH * SEQ * FEAT / 4);

    // 1) W transposes (rounded): Wt[n][k] = tf32(W[k][n])
    dim3 tw(HID / 32, FEAT / 32, 1);
    transpose_tf32<<<tw, dim3(32, 8)>>>(Wq, wqt, FEAT, HID, 0, 0);
    transpose_tf32<<<tw, dim3(32, 8)>>>(Wk, wkt, FEAT, HID, 0, 0);
    transpose_tf32<<<tw, dim3(32, 8)>>>(Wv, wvt, FEAT, HID, 0, 0);

    // 2) QKV projections: [16384,1024] @ Wt^T + bias, outputs tf32-rounded
    dim3 gqkv(HID / GBN, (BATCH * SEQ) / GBM, 1);
    gemm_mma<true, true><<<gqkv, 256, GEMM_SMEM>>>(xc, wqt, bq, q, FEAT, HID, 1.0f, 0, 0, 0);
    gemm_mma<true, true><<<gqkv, 256, GEMM_SMEM>>>(xc, wkt, bk, k, FEAT, HID, 1.0f, 0, 0, 0);
    gemm_mma<true, true><<<gqkv, 256, GEMM_SMEM>>>(xc, wvt, bv, v, FEAT, HID, 1.0f, 0, 0, 0);

    // 3) scores = (Q K^T)/32 per batch
    dim3 gs(SEQ / GBN, SEQ / GBM, BATCH);
    gemm_mma<false, false><<<gs, 256, GEMM_SMEM>>>(q, k, nullptr, p, HID, SEQ, 1.0f / 32.0f,
                                                   (long long)SEQ * HID,
                                                   (long long)SEQ * HID,
                                                   (long long)SEQ * SEQ);

    // 4) softmax rows (stores tf32-rounded probs)
    softmax_rows<<<BATCH * SEQ, 256>>>(p);

    // 5) V^T per batch: vt[h][s] = v[s][h]
    dim3 tv(HID / 32, SEQ / 32, BATCH);
    transpose_tf32<<<tv, dim3(32, 8)>>>(v, vt, SEQ, HID,
                                        (long long)SEQ * HID, (long long)HID * SEQ);

    // 6) out = P @ V (per batch): A=P [4096,4096], B=vt [1024,4096]
    dim3 go(HID / GBN, SEQ / GBM, BATCH);
    gemm_mma<false, false><<<go, 256, GEMM_SMEM>>>(p, vt, nullptr, out, SEQ, HID, 1.0f,
                                                   (long long)SEQ * SEQ,
                                                   (long long)HID * SEQ,
                                                   (long long)SEQ * HID);
}